// round 6
// baseline (speedup 1.0000x reference)
#include <cuda_runtime.h>
#include <cuda_bf16.h>
#include <cstdint>

#define D 128
#define MAX_NODES 100000
#define MAX_EDGES 1600000

// Scratch (no cudaMalloc allowed).
__device__ float g_agg[(size_t)MAX_NODES * D];
__device__ int   g_deg[MAX_NODES];
__device__ int   g_off[MAX_NODES + 1];
__device__ int   g_pos[MAX_NODES];
__device__ int2  g_edges[MAX_EDGES];   // {src, __float_as_int(val)}

// ---------------------------------------------------------------------------
// Kernel 1: zero degree counters.
// ---------------------------------------------------------------------------
__global__ void zero_deg_kernel(int n) {
    int i = blockIdx.x * blockDim.x + threadIdx.x;
    int stride = gridDim.x * blockDim.x;
    for (; i < n; i += stride) g_deg[i] = 0;
}

// ---------------------------------------------------------------------------
// Kernel 2: degree histogram (int REDs, spread addresses — cheap).
// ---------------------------------------------------------------------------
__global__ void hist_kernel(const int* __restrict__ erow, int n_edges) {
    int e = blockIdx.x * blockDim.x + threadIdx.x;
    int stride = gridDim.x * blockDim.x;
    for (; e < n_edges; e += stride)
        atomicAdd(&g_deg[erow[e]], 1);
}

// ---------------------------------------------------------------------------
// Kernel 3: single-block exclusive scan of degrees -> g_off, g_pos.
// 1024 threads, each owns a contiguous chunk; Hillis-Steele over partials.
// ---------------------------------------------------------------------------
__global__ void scan_kernel(int n) {
    __shared__ int sums[1024];
    int t = threadIdx.x;
    int chunk = (n + 1023) >> 10;
    int base = t * chunk;

    int s = 0;
    for (int i = 0; i < chunk; i++) {
        int idx = base + i;
        if (idx < n) s += g_deg[idx];
    }
    sums[t] = s;
    __syncthreads();

    // inclusive scan (read-all / write-all per step)
    for (int off = 1; off < 1024; off <<= 1) {
        int v = (t >= off) ? sums[t - off] : 0;
        __syncthreads();
        sums[t] += v;
        __syncthreads();
    }

    int run = sums[t] - s;   // exclusive prefix for this thread's chunk
    for (int i = 0; i < chunk; i++) {
        int idx = base + i;
        if (idx < n) {
            g_off[idx] = run;
            g_pos[idx] = run;
            run += g_deg[idx];
        }
    }
    if (t == 1023) g_off[n] = run;   // total edge count
}

// ---------------------------------------------------------------------------
// Kernel 4: bin edges into CSR order as {src, val} records.
// ---------------------------------------------------------------------------
__global__ void bin_kernel(const int*   __restrict__ erow,
                           const int*   __restrict__ ecol,
                           const float* __restrict__ evals,
                           int n_edges) {
    int e = blockIdx.x * blockDim.x + threadIdx.x;
    int stride = gridDim.x * blockDim.x;
    for (; e < n_edges; e += stride) {
        int dst = erow[e];
        int p = atomicAdd(&g_pos[dst], 1);
        g_edges[p] = make_int2(ecol[e], __float_as_int(evals[e]));
    }
}

// ---------------------------------------------------------------------------
// Kernel 5: aggregate. One warp per dst node: broadcast edge record,
// gather x[src] float4 per lane, FMA in registers, single store. No atomics.
// ---------------------------------------------------------------------------
__global__ void agg_kernel(const float* __restrict__ x, int n_nodes) {
    int warp = (blockIdx.x * blockDim.x + threadIdx.x) >> 5;
    if (warp >= n_nodes) return;
    int lane = threadIdx.x & 31;

    int beg = g_off[warp];
    int end = g_off[warp + 1];

    const float4* x4 = reinterpret_cast<const float4*>(x);
    float4 acc = make_float4(0.f, 0.f, 0.f, 0.f);

    #pragma unroll 4
    for (int p = beg; p < end; p++) {
        int2 rec = __ldg(&g_edges[p]);              // broadcast across warp
        float v = __int_as_float(rec.y);
        float4 xv = x4[(size_t)rec.x * 32 + lane];  // gather, mostly L2 hits
        acc.x = fmaf(v, xv.x, acc.x);
        acc.y = fmaf(v, xv.y, acc.y);
        acc.z = fmaf(v, xv.z, acc.z);
        acc.w = fmaf(v, xv.w, acc.w);
    }

    reinterpret_cast<float4*>(g_agg)[(size_t)warp * 32 + lane] = acc;
}

// ---------------------------------------------------------------------------
// Kernel 6: C[n,128] = agg[n,128] @ W[128,128], fp32 (unchanged).
// ---------------------------------------------------------------------------
__global__ void gemm_kernel(const float* __restrict__ W,
                            float* __restrict__ C, int n) {
    extern __shared__ float sm[];
    float* Ws = sm;              // [128][128]
    float* As = sm + 128 * 128;  // [128][128]

    int tid  = threadIdx.x;
    int row0 = blockIdx.x * 128;

    {
        const float4* Wg = reinterpret_cast<const float4*>(W);
        float4* Wsh = reinterpret_cast<float4*>(Ws);
        #pragma unroll
        for (int i = 0; i < 16; i++)
            Wsh[tid + i * 256] = Wg[tid + i * 256];
    }
    {
        float4* Ash = reinterpret_cast<float4*>(As);
        #pragma unroll
        for (int i = 0; i < 16; i++) {
            int idx = tid + i * 256;
            int r = idx >> 5;
            float4 val = make_float4(0.f, 0.f, 0.f, 0.f);
            if (row0 + r < n)
                val = reinterpret_cast<const float4*>(
                          g_agg + (size_t)(row0 + r) * D)[idx & 31];
            Ash[idx] = val;
        }
    }
    __syncthreads();

    int cg = tid & 15;
    int rg = tid >> 4;

    float acc[8][8];
    #pragma unroll
    for (int i = 0; i < 8; i++)
        #pragma unroll
        for (int j = 0; j < 8; j++) acc[i][j] = 0.f;

    #pragma unroll 4
    for (int k = 0; k < 128; k++) {
        float a[8];
        #pragma unroll
        for (int i = 0; i < 8; i++)
            a[i] = As[(rg * 8 + i) * 128 + k];
        const float4* wrow = reinterpret_cast<const float4*>(Ws + k * 128 + cg * 8);
        float4 b0 = wrow[0];
        float4 b1 = wrow[1];
        float b[8] = {b0.x, b0.y, b0.z, b0.w, b1.x, b1.y, b1.z, b1.w};
        #pragma unroll
        for (int i = 0; i < 8; i++)
            #pragma unroll
            for (int j = 0; j < 8; j++)
                acc[i][j] = fmaf(a[i], b[j], acc[i][j]);
    }

    #pragma unroll
    for (int i = 0; i < 8; i++) {
        int r = row0 + rg * 8 + i;
        if (r < n) {
            float4* out = reinterpret_cast<float4*>(C + (size_t)r * D + cg * 8);
            out[0] = make_float4(acc[i][0], acc[i][1], acc[i][2], acc[i][3]);
            out[1] = make_float4(acc[i][4], acc[i][5], acc[i][6], acc[i][7]);
        }
    }
}

// ---------------------------------------------------------------------------
// Launch
// ---------------------------------------------------------------------------
extern "C" void kernel_launch(void* const* d_in, const int* in_sizes, int n_in,
                              void* d_out, int out_size) {
    const float* x     = (const float*)d_in[0];
    const int*   erow  = (const int*)  d_in[1];
    const int*   ecol  = (const int*)  d_in[2];
    const float* evals = (const float*)d_in[3];
    const float* W     = (const float*)d_in[4];
    float*       out   = (float*)d_out;

    int n_nodes = in_sizes[0] / D;   // 100000
    int n_edges = in_sizes[1];       // 1600000

    // 1) zero degree counters
    zero_deg_kernel<<<256, 256>>>(n_nodes);

    // 2) degree histogram
    {
        int threads = 256;
        int blocks = (n_edges + threads - 1) / threads;
        if (blocks > 4096) blocks = 4096;
        hist_kernel<<<blocks, threads>>>(erow, n_edges);
    }

    // 3) exclusive scan -> offsets + cursors
    scan_kernel<<<1, 1024>>>(n_nodes);

    // 4) bin edges into CSR order
    {
        int threads = 256;
        int blocks = (n_edges + threads - 1) / threads;
        if (blocks > 4096) blocks = 4096;
        bin_kernel<<<blocks, threads>>>(erow, ecol, evals, n_edges);
    }

    // 5) aggregate (warp per node, no atomics)
    {
        int threads = 256;                       // 8 warps/block
        int blocks = (n_nodes + 7) / 8;
        agg_kernel<<<blocks, threads>>>(x, n_nodes);
    }

    // 6) dense GEMM agg @ W -> out
    {
        int smem = 2 * 128 * 128 * sizeof(float);
        cudaFuncSetAttribute(gemm_kernel,
                             cudaFuncAttributeMaxDynamicSharedMemorySize, smem);
        int blocks = (n_nodes + 127) / 128;
        gemm_kernel<<<blocks, 256, smem>>>(W, out, n_nodes);
    }
}

// round 9
// speedup vs baseline: 1.4038x; 1.4038x over previous
#include <cuda_runtime.h>
#include <cuda_bf16.h>
#include <cstdint>

#define D 128
#define MAX_NODES 100000

// Scratch (no cudaMalloc allowed).
__device__ float    g_agg[(size_t)MAX_NODES * D];
__device__ ushort   g_Whi[D * D];   // bf16 W^T hi: [n][k]
__device__ ushort   g_Wlo[D * D];   // bf16 W^T lo: [n][k]

// ===========================================================================
// Kernel 1: zero the aggregation scratch (float4 grid-stride).
// ===========================================================================
__global__ void zero_agg_kernel(int n4) {
    int i = blockIdx.x * blockDim.x + threadIdx.x;
    int stride = gridDim.x * blockDim.x;
    float4 z = make_float4(0.f, 0.f, 0.f, 0.f);
    float4* p = reinterpret_cast<float4*>(g_agg);
    for (; i < n4; i += stride) p[i] = z;
}

// ===========================================================================
// Kernel 2: edge scatter (round-4 proven version). One warp per edge:
// lane l loads float4 of x[src], scales, RED.v4.f32 to agg[dst].
// ===========================================================================
__global__ void scatter_kernel(const float* __restrict__ x,
                               const int*   __restrict__ erow,
                               const int*   __restrict__ ecol,
                               const float* __restrict__ evals,
                               int n_edges) {
    int e = (blockIdx.x * blockDim.x + threadIdx.x) >> 5;
    if (e >= n_edges) return;
    int lane = threadIdx.x & 31;

    int dst = erow[e];
    int src = ecol[e];
    float v = evals[e];

    const float4* xr = reinterpret_cast<const float4*>(x + (size_t)src * D);
    float4 m = xr[lane];
    m.x *= v; m.y *= v; m.z *= v; m.w *= v;

    float* d = g_agg + (size_t)dst * D + lane * 4;
    asm volatile("red.global.add.v4.f32 [%0], {%1, %2, %3, %4};"
                 :: "l"(d), "f"(m.x), "f"(m.y), "f"(m.z), "f"(m.w)
                 : "memory");
}

// ===========================================================================
// Kernel 3: W prep. Split fp32 W into bf16 hi/lo and transpose to [n][k].
// W input is [k][n] row-major.
// ===========================================================================
__global__ void wprep_kernel(const float* __restrict__ W) {
    int i = blockIdx.x * blockDim.x + threadIdx.x;
    if (i >= D * D) return;
    int k = i >> 7, n = i & 127;
    float w = W[i];
    __nv_bfloat16 h = __float2bfloat16(w);
    float r = w - __bfloat162float(h);
    __nv_bfloat16 l = __float2bfloat16(r);
    g_Whi[n * D + k] = __bfloat16_as_ushort(h);
    g_Wlo[n * D + k] = __bfloat16_as_ushort(l);
}

// ===========================================================================
// Kernel 4: tensor-core GEMM via mma.sync m16n8k16 bf16 (split, 3 terms).
// C[n,128] = agg[n,128] @ W[128,128], fp32 accumulate in registers.
// Block: 128-row tile, 256 threads, 8 warps in 2(M)x4(N); warp = 64x32 out.
// ===========================================================================
#define P 136                                    // smem pitch in bf16 elems
#define TILE_BYTES (128 * P * 2)                 // 34816
#define SMEM_AHI 0
#define SMEM_ALO (TILE_BYTES)
#define SMEM_BHI (2 * TILE_BYTES)
#define SMEM_BLO (3 * TILE_BYTES)
#define SMEM_TOTAL (4 * TILE_BYTES)              // 139264

__device__ __forceinline__ uint32_t smem_u32(const void* p) {
    uint32_t a;
    asm("{ .reg .u64 t; cvta.to.shared.u64 t, %1; cvt.u32.u64 %0, t; }"
        : "=r"(a) : "l"(p));
    return a;
}

__device__ __forceinline__ void ldsm_x4(uint32_t addr, uint32_t& r0, uint32_t& r1,
                                        uint32_t& r2, uint32_t& r3) {
    asm volatile("ldmatrix.sync.aligned.m8n8.x4.shared.b16 {%0,%1,%2,%3}, [%4];"
                 : "=r"(r0), "=r"(r1), "=r"(r2), "=r"(r3) : "r"(addr));
}

__device__ __forceinline__ void mma_bf16(float& d0, float& d1, float& d2, float& d3,
                                         uint32_t a0, uint32_t a1, uint32_t a2, uint32_t a3,
                                         uint32_t b0, uint32_t b1) {
    asm volatile("mma.sync.aligned.m16n8k16.row.col.f32.bf16.bf16.f32 "
                 "{%0,%1,%2,%3}, {%4,%5,%6,%7}, {%8,%9}, {%0,%1,%2,%3};"
                 : "+f"(d0), "+f"(d1), "+f"(d2), "+f"(d3)
                 : "r"(a0), "r"(a1), "r"(a2), "r"(a3), "r"(b0), "r"(b1));
}

__device__ __forceinline__ void split2(float a, float b, uint32_t& h, uint32_t& l) {
    __nv_bfloat16 ha = __float2bfloat16(a);
    __nv_bfloat16 hb = __float2bfloat16(b);
    __nv_bfloat16 la = __float2bfloat16(a - __bfloat162float(ha));
    __nv_bfloat16 lb = __float2bfloat16(b - __bfloat162float(hb));
    h = (uint32_t)__bfloat16_as_ushort(ha) | ((uint32_t)__bfloat16_as_ushort(hb) << 16);
    l = (uint32_t)__bfloat16_as_ushort(la) | ((uint32_t)__bfloat16_as_ushort(lb) << 16);
}

__global__ void __launch_bounds__(256, 1)
gemm_mma_kernel(float* __restrict__ C, int n) {
    extern __shared__ char smem[];
    uint32_t sbase = smem_u32(smem);

    int tid  = threadIdx.x;
    int lane = tid & 31;
    int wid  = tid >> 5;
    int row0 = blockIdx.x << 7;

    // ---- Stage B (hi+lo) from prepped global images, pitch P ----
    {
        const uint4* sh = reinterpret_cast<const uint4*>(g_Whi);
        const uint4* sl = reinterpret_cast<const uint4*>(g_Wlo);
        #pragma unroll
        for (int i = 0; i < 8; i++) {
            int idx = tid + i * 256;       // 2048 uint4 per image
            int r = idx >> 4, c = idx & 15;
            int off = r * (P * 2) + c * 16;
            *reinterpret_cast<uint4*>(smem + SMEM_BHI + off) = sh[idx];
            *reinterpret_cast<uint4*>(smem + SMEM_BLO + off) = sl[idx];
        }
    }

    // ---- Load + split A tile: fp32 -> bf16 hi/lo in smem ----
    {
        const float4* ag = reinterpret_cast<const float4*>(g_agg);
        #pragma unroll
        for (int i = 0; i < 16; i++) {
            int idx = tid + i * 256;       // 4096 float4
            int r = idx >> 5, c4 = idx & 31;
            float4 v = make_float4(0.f, 0.f, 0.f, 0.f);
            if (row0 + r < n) v = ag[(size_t)(row0 + r) * 32 + c4];
            uint32_t h0, l0, h1, l1;
            split2(v.x, v.y, h0, l0);
            split2(v.z, v.w, h1, l1);
            int off = r * (P * 2) + c4 * 8;
            *reinterpret_cast<uint2*>(smem + SMEM_AHI + off) = make_uint2(h0, h1);
            *reinterpret_cast<uint2*>(smem + SMEM_ALO + off) = make_uint2(l0, l1);
        }
    }
    __syncthreads();

    // ---- Warp tiling: 2 (M) x 4 (N); warp -> 64x32 output ----
    int wm = wid >> 2;            // 0..1
    int wn = wid & 3;             // 0..3

    // ldmatrix lane offsets (in bf16 elements)
    int loffA = (lane & 15) * P + (lane >> 4) * 8;
    int loffB = ((lane & 7) + ((lane >> 4) & 1) * 8) * P + ((lane >> 3) & 1) * 8;

    uint32_t aHi = sbase + SMEM_AHI + 2 * (loffA + wm * 64 * P);
    uint32_t aLo = sbase + SMEM_ALO + 2 * (loffA + wm * 64 * P);
    uint32_t bHi = sbase + SMEM_BHI + 2 * (loffB + wn * 32 * P);
    uint32_t bLo = sbase + SMEM_BLO + 2 * (loffB + wn * 32 * P);

    float acc[4][4][4];
    #pragma unroll
    for (int i = 0; i < 4; i++)
        #pragma unroll
        for (int j = 0; j < 4; j++)
            #pragma unroll
            for (int q = 0; q < 4; q++) acc[i][j][q] = 0.f;

    #pragma unroll
    for (int ks = 0; ks < 8; ks++) {
        uint32_t ah[4][4], al[4][4];
        #pragma unroll
        for (int mt = 0; mt < 4; mt++) {
            uint32_t off = (uint32_t)(mt * 16 * P * 2 + ks * 32);
            ldsm_x4(aHi + off, ah[mt][0], ah[mt][1], ah[mt][2], ah[mt][3]);
            ldsm_x4(aLo + off, al[mt][0], al[mt][1], al[mt][2], al[mt][3]);
        }
        uint32_t bh[4][2], bl[4][2];
        #pragma unroll
        for (int nt2 = 0; nt2 < 2; nt2++) {
            uint32_t off = (uint32_t)(nt2 * 16 * P * 2 + ks * 32);
            ldsm_x4(bHi + off, bh[nt2 * 2][0], bh[nt2 * 2][1],
                               bh[nt2 * 2 + 1][0], bh[nt2 * 2 + 1][1]);
            ldsm_x4(bLo + off, bl[nt2 * 2][0], bl[nt2 * 2][1],
                               bl[nt2 * 2 + 1][0], bl[nt2 * 2 + 1][1]);
        }
        #pragma unroll
        for (int mt = 0; mt < 4; mt++)
            #pragma unroll
            for (int nt = 0; nt < 4; nt++) {
                float* d = acc[mt][nt];
                mma_bf16(d[0], d[1], d[2], d[3],
                         ah[mt][0], ah[mt][1], ah[mt][2], ah[mt][3],
                         bh[nt][0], bh[nt][1]);                 // Ahi*Bhi
                mma_bf16(d[0], d[1], d[2], d[3],
                         ah[mt][0], ah[mt][1], ah[mt][2], ah[mt][3],
                         bl[nt][0], bl[nt][1]);                 // Ahi*Blo
                mma_bf16(d[0], d[1], d[2], d[3],
                         al[mt][0], al[mt][1], al[mt][2], al[mt][3],
                         bh[nt][0], bh[nt][1]);                 // Alo*Bhi
            }
    }

    // ---- Epilogue: acc regs -> C. Thread t: rows t/4 and t/4+8, cols 2*(t%4).
    int tr = lane >> 2;
    int tc = (lane & 3) * 2;
    #pragma unroll
    for (int mt = 0; mt < 4; mt++) {
        int r_a = row0 + wm * 64 + mt * 16 + tr;
        int r_b = r_a + 8;
        #pragma unroll
        for (int nt = 0; nt < 4; nt++) {
            int col = wn * 32 + nt * 8 + tc;
            if (r_a < n)
                *reinterpret_cast<float2*>(C + (size_t)r_a * D + col) =
                    make_float2(acc[mt][nt][0], acc[mt][nt][1]);
            if (r_b < n)
                *reinterpret_cast<float2*>(C + (size_t)r_b * D + col) =
                    make_float2(acc[mt][nt][2], acc[mt][nt][3]);
        }
    }
}

// ===========================================================================
// Launch
// ===========================================================================
extern "C" void kernel_launch(void* const* d_in, const int* in_sizes, int n_in,
                              void* d_out, int out_size) {
    const float* x     = (const float*)d_in[0];
    const int*   erow  = (const int*)  d_in[1];
    const int*   ecol  = (const int*)  d_in[2];
    const float* evals = (const float*)d_in[3];
    const float* W     = (const float*)d_in[4];
    float*       out   = (float*)d_out;

    int n_nodes = in_sizes[0] / D;   // 100000
    int n_edges = in_sizes[1];       // 1600000

    // 1) zero agg scratch
    {
        int n4 = n_nodes * (D / 4);
        int threads = 256;
        int blocks = (n4 + threads * 4 - 1) / (threads * 4);
        if (blocks > 8192) blocks = 8192;
        zero_agg_kernel<<<blocks, threads>>>(n4);
    }
    // 2) W prep (split + transpose)
    wprep_kernel<<<64, 256>>>(W);
    // 3) edge scatter (1 warp per edge)
    {
        int threads = 256;
        int warps_per_block = threads / 32;
        int blocks = (n_edges + warps_per_block - 1) / warps_per_block;
        scatter_kernel<<<blocks, threads>>>(x, erow, ecol, evals, n_edges);
    }
    // 4) tensor-core GEMM agg @ W -> out
    {
        cudaFuncSetAttribute(gemm_mma_kernel,
                             cudaFuncAttributeMaxDynamicSharedMemorySize, SMEM_TOTAL);
        int blocks = (n_nodes + 127) / 128;
        gemm_mma_kernel<<<blocks, 256, SMEM_TOTAL>>>(out, n_nodes);
    }
}

// round 10
// speedup vs baseline: 2.1521x; 1.5331x over previous
#include <cuda_runtime.h>
#include <cuda_bf16.h>
#include <cstdint>

#define D 128
#define MAX_NODES 100000
#define MAX_EDGES 1600000

// Scratch (no cudaMalloc allowed).
__device__ float    g_agg[(size_t)MAX_NODES * D];
__device__ ushort   g_Whi[D * D];   // bf16 W^T hi: [n][k]
__device__ ushort   g_Wlo[D * D];   // bf16 W^T lo: [n][k]
__device__ int      g_deg[MAX_NODES];
__device__ int      g_off[MAX_NODES + 1];
__device__ int      g_pos[MAX_NODES];
__device__ int      g_bsum[128];
__device__ int2     g_edges[MAX_EDGES];   // {src, __float_as_int(val)}

// ===========================================================================
// CSR build: zero degrees -> histogram -> 3-phase scan -> bin
// ===========================================================================
__global__ void zero_deg_kernel(int n) {
    int i = blockIdx.x * blockDim.x + threadIdx.x;
    int stride = gridDim.x * blockDim.x;
    for (; i < n; i += stride) g_deg[i] = 0;
}

// 4 edges per thread via int4 load (MLP=4 on the atomics).
__global__ void hist_kernel(const int* __restrict__ erow, int n_edges) {
    int t = blockIdx.x * blockDim.x + threadIdx.x;
    int base = t * 4;
    if (base + 3 < n_edges) {
        int4 r = reinterpret_cast<const int4*>(erow)[t];
        atomicAdd(&g_deg[r.x], 1);
        atomicAdd(&g_deg[r.y], 1);
        atomicAdd(&g_deg[r.z], 1);
        atomicAdd(&g_deg[r.w], 1);
    } else {
        for (int e = base; e < n_edges; e++) atomicAdd(&g_deg[erow[e]], 1);
    }
}

// Phase A: per-block (1024 elems) exclusive scan; block sum to g_bsum.
__global__ void scanA_kernel(int n) {
    __shared__ int s[1024];
    int t = threadIdx.x;
    int i = blockIdx.x * 1024 + t;
    int v = (i < n) ? g_deg[i] : 0;
    s[t] = v;
    __syncthreads();
    for (int off = 1; off < 1024; off <<= 1) {
        int u = (t >= off) ? s[t - off] : 0;
        __syncthreads();
        s[t] += u;
        __syncthreads();
    }
    if (i < n) g_off[i] = s[t] - v;       // exclusive within block
    if (t == 1023) g_bsum[blockIdx.x] = s[1023];
}

// Phase B: single small block scans <=128 block sums (exclusive); total -> g_off[n].
__global__ void scanB_kernel(int nb, int n) {
    __shared__ int s[128];
    int t = threadIdx.x;
    int v = (t < nb) ? g_bsum[t] : 0;
    s[t] = v;
    __syncthreads();
    for (int off = 1; off < 128; off <<= 1) {
        int u = (t >= off) ? s[t - off] : 0;
        __syncthreads();
        s[t] += u;
        __syncthreads();
    }
    if (t < nb) g_bsum[t] = s[t] - v;     // exclusive block offsets
    if (t == 127) g_off[n] = s[127];      // total
}

// Phase C: add block offsets, init cursors.
__global__ void scanC_kernel(int n) {
    int i = blockIdx.x * 1024 + threadIdx.x;
    if (i < n) {
        int o = g_off[i] + g_bsum[blockIdx.x];
        g_off[i] = o;
        g_pos[i] = o;
    }
}

// Bin edges into CSR order; 4 edges per thread (vector loads, MLP on atomics).
__global__ void bin_kernel(const int*   __restrict__ erow,
                           const int*   __restrict__ ecol,
                           const float* __restrict__ evals,
                           int n_edges) {
    int t = blockIdx.x * blockDim.x + threadIdx.x;
    int base = t * 4;
    if (base + 3 < n_edges) {
        int4   rr = reinterpret_cast<const int4*>(erow)[t];
        int4   cc = reinterpret_cast<const int4*>(ecol)[t];
        float4 vv = reinterpret_cast<const float4*>(evals)[t];
        int p0 = atomicAdd(&g_pos[rr.x], 1);
        int p1 = atomicAdd(&g_pos[rr.y], 1);
        int p2 = atomicAdd(&g_pos[rr.z], 1);
        int p3 = atomicAdd(&g_pos[rr.w], 1);
        g_edges[p0] = make_int2(cc.x, __float_as_int(vv.x));
        g_edges[p1] = make_int2(cc.y, __float_as_int(vv.y));
        g_edges[p2] = make_int2(cc.z, __float_as_int(vv.z));
        g_edges[p3] = make_int2(cc.w, __float_as_int(vv.w));
    } else {
        for (int e = base; e < n_edges; e++) {
            int p = atomicAdd(&g_pos[erow[e]], 1);
            g_edges[p] = make_int2(ecol[e], __float_as_int(evals[e]));
        }
    }
}

// ===========================================================================
// Aggregate: warp per dst node, rolling prefetch depth 4 so gathers have
// MLP>=4 and no record->gather serial chain. No atomics; writes every row,
// so no zero_agg pass is needed.
// ===========================================================================
__global__ void agg_kernel(const float* __restrict__ x, int n_nodes) {
    int warp = (blockIdx.x * blockDim.x + threadIdx.x) >> 5;
    if (warp >= n_nodes) return;
    int lane = threadIdx.x & 31;

    int beg = g_off[warp];
    int end = g_off[warp + 1];

    const float4* x4 = reinterpret_cast<const float4*>(x);
    float4 acc = make_float4(0.f, 0.f, 0.f, 0.f);

    int2 pf[4];
    #pragma unroll
    for (int j = 0; j < 4; j++)
        pf[j] = (beg + j < end) ? __ldg(&g_edges[beg + j]) : make_int2(0, 0);

    for (int p = beg; p < end; p += 4) {
        int2 cur[4];
        #pragma unroll
        for (int j = 0; j < 4; j++) cur[j] = pf[j];
        #pragma unroll
        for (int j = 0; j < 4; j++)
            pf[j] = (p + 4 + j < end) ? __ldg(&g_edges[p + 4 + j]) : make_int2(0, 0);
        #pragma unroll
        for (int j = 0; j < 4; j++) {
            if (p + j < end) {
                float v = __int_as_float(cur[j].y);
                float4 g = x4[(size_t)cur[j].x * 32 + lane];
                acc.x = fmaf(v, g.x, acc.x);
                acc.y = fmaf(v, g.y, acc.y);
                acc.z = fmaf(v, g.z, acc.z);
                acc.w = fmaf(v, g.w, acc.w);
            }
        }
    }

    reinterpret_cast<float4*>(g_agg)[(size_t)warp * 32 + lane] = acc;
}

// ===========================================================================
// W prep. Split fp32 W into bf16 hi/lo and transpose to [n][k].
// ===========================================================================
__global__ void wprep_kernel(const float* __restrict__ W) {
    int i = blockIdx.x * blockDim.x + threadIdx.x;
    if (i >= D * D) return;
    int k = i >> 7, n = i & 127;
    float w = W[i];
    __nv_bfloat16 h = __float2bfloat16(w);
    float r = w - __bfloat162float(h);
    __nv_bfloat16 l = __float2bfloat16(r);
    g_Whi[n * D + k] = __bfloat16_as_ushort(h);
    g_Wlo[n * D + k] = __bfloat16_as_ushort(l);
}

// ===========================================================================
// Tensor-core GEMM via mma.sync m16n8k16 bf16 (split, 3 terms) — unchanged.
// ===========================================================================
#define P 136
#define TILE_BYTES (128 * P * 2)
#define SMEM_AHI 0
#define SMEM_ALO (TILE_BYTES)
#define SMEM_BHI (2 * TILE_BYTES)
#define SMEM_BLO (3 * TILE_BYTES)
#define SMEM_TOTAL (4 * TILE_BYTES)

__device__ __forceinline__ uint32_t smem_u32(const void* p) {
    uint32_t a;
    asm("{ .reg .u64 t; cvta.to.shared.u64 t, %1; cvt.u32.u64 %0, t; }"
        : "=r"(a) : "l"(p));
    return a;
}

__device__ __forceinline__ void ldsm_x4(uint32_t addr, uint32_t& r0, uint32_t& r1,
                                        uint32_t& r2, uint32_t& r3) {
    asm volatile("ldmatrix.sync.aligned.m8n8.x4.shared.b16 {%0,%1,%2,%3}, [%4];"
                 : "=r"(r0), "=r"(r1), "=r"(r2), "=r"(r3) : "r"(addr));
}

__device__ __forceinline__ void mma_bf16(float& d0, float& d1, float& d2, float& d3,
                                         uint32_t a0, uint32_t a1, uint32_t a2, uint32_t a3,
                                         uint32_t b0, uint32_t b1) {
    asm volatile("mma.sync.aligned.m16n8k16.row.col.f32.bf16.bf16.f32 "
                 "{%0,%1,%2,%3}, {%4,%5,%6,%7}, {%8,%9}, {%0,%1,%2,%3};"
                 : "+f"(d0), "+f"(d1), "+f"(d2), "+f"(d3)
                 : "r"(a0), "r"(a1), "r"(a2), "r"(a3), "r"(b0), "r"(b1));
}

__device__ __forceinline__ void split2(float a, float b, uint32_t& h, uint32_t& l) {
    __nv_bfloat16 ha = __float2bfloat16(a);
    __nv_bfloat16 hb = __float2bfloat16(b);
    __nv_bfloat16 la = __float2bfloat16(a - __bfloat162float(ha));
    __nv_bfloat16 lb = __float2bfloat16(b - __bfloat162float(hb));
    h = (uint32_t)__bfloat16_as_ushort(ha) | ((uint32_t)__bfloat16_as_ushort(hb) << 16);
    l = (uint32_t)__bfloat16_as_ushort(la) | ((uint32_t)__bfloat16_as_ushort(lb) << 16);
}

__global__ void __launch_bounds__(256, 1)
gemm_mma_kernel(float* __restrict__ C, int n) {
    extern __shared__ char smem[];
    uint32_t sbase = smem_u32(smem);

    int tid  = threadIdx.x;
    int lane = tid & 31;
    int wid  = tid >> 5;
    int row0 = blockIdx.x << 7;

    {
        const uint4* sh = reinterpret_cast<const uint4*>(g_Whi);
        const uint4* sl = reinterpret_cast<const uint4*>(g_Wlo);
        #pragma unroll
        for (int i = 0; i < 8; i++) {
            int idx = tid + i * 256;
            int r = idx >> 4, c = idx & 15;
            int off = r * (P * 2) + c * 16;
            *reinterpret_cast<uint4*>(smem + SMEM_BHI + off) = sh[idx];
            *reinterpret_cast<uint4*>(smem + SMEM_BLO + off) = sl[idx];
        }
    }
    {
        const float4* ag = reinterpret_cast<const float4*>(g_agg);
        #pragma unroll
        for (int i = 0; i < 16; i++) {
            int idx = tid + i * 256;
            int r = idx >> 5, c4 = idx & 31;
            float4 v = make_float4(0.f, 0.f, 0.f, 0.f);
            if (row0 + r < n) v = ag[(size_t)(row0 + r) * 32 + c4];
            uint32_t h0, l0, h1, l1;
            split2(v.x, v.y, h0, l0);
            split2(v.z, v.w, h1, l1);
            int off = r * (P * 2) + c4 * 8;
            *reinterpret_cast<uint2*>(smem + SMEM_AHI + off) = make_uint2(h0, h1);
            *reinterpret_cast<uint2*>(smem + SMEM_ALO + off) = make_uint2(l0, l1);
        }
    }
    __syncthreads();

    int wm = wid >> 2;
    int wn = wid & 3;

    int loffA = (lane & 15) * P + (lane >> 4) * 8;
    int loffB = ((lane & 7) + ((lane >> 4) & 1) * 8) * P + ((lane >> 3) & 1) * 8;

    uint32_t aHi = sbase + SMEM_AHI + 2 * (loffA + wm * 64 * P);
    uint32_t aLo = sbase + SMEM_ALO + 2 * (loffA + wm * 64 * P);
    uint32_t bHi = sbase + SMEM_BHI + 2 * (loffB + wn * 32 * P);
    uint32_t bLo = sbase + SMEM_BLO + 2 * (loffB + wn * 32 * P);

    float acc[4][4][4];
    #pragma unroll
    for (int i = 0; i < 4; i++)
        #pragma unroll
        for (int j = 0; j < 4; j++)
            #pragma unroll
            for (int q = 0; q < 4; q++) acc[i][j][q] = 0.f;

    #pragma unroll
    for (int ks = 0; ks < 8; ks++) {
        uint32_t ah[4][4], al[4][4];
        #pragma unroll
        for (int mt = 0; mt < 4; mt++) {
            uint32_t off = (uint32_t)(mt * 16 * P * 2 + ks * 32);
            ldsm_x4(aHi + off, ah[mt][0], ah[mt][1], ah[mt][2], ah[mt][3]);
            ldsm_x4(aLo + off, al[mt][0], al[mt][1], al[mt][2], al[mt][3]);
        }
        uint32_t bh[4][2], bl[4][2];
        #pragma unroll
        for (int nt2 = 0; nt2 < 2; nt2++) {
            uint32_t off = (uint32_t)(nt2 * 16 * P * 2 + ks * 32);
            ldsm_x4(bHi + off, bh[nt2 * 2][0], bh[nt2 * 2][1],
                               bh[nt2 * 2 + 1][0], bh[nt2 * 2 + 1][1]);
            ldsm_x4(bLo + off, bl[nt2 * 2][0], bl[nt2 * 2][1],
                               bl[nt2 * 2 + 1][0], bl[nt2 * 2 + 1][1]);
        }
        #pragma unroll
        for (int mt = 0; mt < 4; mt++)
            #pragma unroll
            for (int nt = 0; nt < 4; nt++) {
                float* d = acc[mt][nt];
                mma_bf16(d[0], d[1], d[2], d[3],
                         ah[mt][0], ah[mt][1], ah[mt][2], ah[mt][3],
                         bh[nt][0], bh[nt][1]);
                mma_bf16(d[0], d[1], d[2], d[3],
                         ah[mt][0], ah[mt][1], ah[mt][2], ah[mt][3],
                         bl[nt][0], bl[nt][1]);
                mma_bf16(d[0], d[1], d[2], d[3],
                         al[mt][0], al[mt][1], al[mt][2], al[mt][3],
                         bh[nt][0], bh[nt][1]);
            }
    }

    int tr = lane >> 2;
    int tc = (lane & 3) * 2;
    #pragma unroll
    for (int mt = 0; mt < 4; mt++) {
        int r_a = row0 + wm * 64 + mt * 16 + tr;
        int r_b = r_a + 8;
        #pragma unroll
        for (int nt = 0; nt < 4; nt++) {
            int col = wn * 32 + nt * 8 + tc;
            if (r_a < n)
                *reinterpret_cast<float2*>(C + (size_t)r_a * D + col) =
                    make_float2(acc[mt][nt][0], acc[mt][nt][1]);
            if (r_b < n)
                *reinterpret_cast<float2*>(C + (size_t)r_b * D + col) =
                    make_float2(acc[mt][nt][2], acc[mt][nt][3]);
        }
    }
}

// ===========================================================================
// Launch
// ===========================================================================
extern "C" void kernel_launch(void* const* d_in, const int* in_sizes, int n_in,
                              void* d_out, int out_size) {
    const float* x     = (const float*)d_in[0];
    const int*   erow  = (const int*)  d_in[1];
    const int*   ecol  = (const int*)  d_in[2];
    const float* evals = (const float*)d_in[3];
    const float* W     = (const float*)d_in[4];
    float*       out   = (float*)d_out;

    int n_nodes = in_sizes[0] / D;   // 100000
    int n_edges = in_sizes[1];       // 1600000

    int scan_blocks = (n_nodes + 1023) / 1024;   // 98 <= 128

    // CSR build
    zero_deg_kernel<<<128, 256>>>(n_nodes);
    {
        int nthread = (n_edges + 3) / 4;
        hist_kernel<<<(nthread + 255) / 256, 256>>>(erow, n_edges);
    }
    scanA_kernel<<<scan_blocks, 1024>>>(n_nodes);
    scanB_kernel<<<1, 128>>>(scan_blocks, n_nodes);
    scanC_kernel<<<scan_blocks, 1024>>>(n_nodes);
    {
        int nthread = (n_edges + 3) / 4;
        bin_kernel<<<(nthread + 255) / 256, 256>>>(erow, ecol, evals, n_edges);
    }

    // W prep (independent)
    wprep_kernel<<<64, 256>>>(W);

    // Aggregate (warp per node, no atomics, no zero pass)
    agg_kernel<<<(n_nodes + 7) / 8, 256>>>(x, n_nodes);

    // Tensor-core GEMM agg @ W -> out
    {
        cudaFuncSetAttribute(gemm_mma_kernel,
                             cudaFuncAttributeMaxDynamicSharedMemorySize, SMEM_TOTAL);
        int blocks = (n_nodes + 127) / 128;
        gemm_mma_kernel<<<blocks, 256, SMEM_TOTAL>>>(out, n_nodes);
    }
}

// round 11
// speedup vs baseline: 2.2098x; 1.0268x over previous
#include <cuda_runtime.h>
#include <cuda_bf16.h>
#include <cstdint>

#define D 128
#define MAX_NODES 100000
#define MAX_EDGES 1600000

// Scratch (no cudaMalloc allowed).
__device__ float    g_agg[(size_t)MAX_NODES * D];
__device__ ushort   g_Whi[D * D];   // bf16 W^T hi: [n][k]
__device__ ushort   g_Wlo[D * D];   // bf16 W^T lo: [n][k]
__device__ int      g_deg[MAX_NODES];
__device__ int      g_off[MAX_NODES + 1];
__device__ int      g_pos[MAX_NODES];
__device__ int      g_bsum[128];
__device__ int2     g_edges[MAX_EDGES];   // {src, __float_as_int(val)}

// ===========================================================================
// Kernel 1 (merged): blocks [0,128) zero degree counters;
//                    blocks [128,192) do W split+transpose.
// ===========================================================================
__global__ void prep_kernel(const float* __restrict__ W, int n) {
    if (blockIdx.x < 128) {
        int i = blockIdx.x * blockDim.x + threadIdx.x;
        int stride = 128 * blockDim.x;
        for (; i < n; i += stride) g_deg[i] = 0;
    } else {
        int i = (blockIdx.x - 128) * blockDim.x + threadIdx.x;
        if (i >= D * D) return;
        int k = i >> 7, nn = i & 127;
        float w = W[i];
        __nv_bfloat16 h = __float2bfloat16(w);
        float r = w - __bfloat162float(h);
        __nv_bfloat16 l = __float2bfloat16(r);
        g_Whi[nn * D + k] = __bfloat16_as_ushort(h);
        g_Wlo[nn * D + k] = __bfloat16_as_ushort(l);
    }
}

// ===========================================================================
// Histogram: 4 edges per thread via int4 load (MLP=4 on the atomics).
// ===========================================================================
__global__ void hist_kernel(const int* __restrict__ erow, int n_edges) {
    int t = blockIdx.x * blockDim.x + threadIdx.x;
    int base = t * 4;
    if (base + 3 < n_edges) {
        int4 r = reinterpret_cast<const int4*>(erow)[t];
        atomicAdd(&g_deg[r.x], 1);
        atomicAdd(&g_deg[r.y], 1);
        atomicAdd(&g_deg[r.z], 1);
        atomicAdd(&g_deg[r.w], 1);
    } else {
        for (int e = base; e < n_edges; e++) atomicAdd(&g_deg[erow[e]], 1);
    }
}

// ===========================================================================
// Scan phase A: per-block (1024 elems) exclusive scan; block sum to g_bsum.
// ===========================================================================
__global__ void scanA_kernel(int n) {
    __shared__ int s[1024];
    int t = threadIdx.x;
    int i = blockIdx.x * 1024 + t;
    int v = (i < n) ? g_deg[i] : 0;
    s[t] = v;
    __syncthreads();
    for (int off = 1; off < 1024; off <<= 1) {
        int u = (t >= off) ? s[t - off] : 0;
        __syncthreads();
        s[t] += u;
        __syncthreads();
    }
    if (i < n) g_off[i] = s[t] - v;       // exclusive within block
    if (t == 1023) g_bsum[blockIdx.x] = s[1023];
}

// ===========================================================================
// Scan phase C (scanB folded in): each block reduces bsum[0..blockIdx-1]
// itself, adds to its elements, inits cursors. Last block writes total.
// ===========================================================================
__global__ void scanC_kernel(int nb, int n) {
    __shared__ int s[128];
    int t = threadIdx.x;
    int bid = blockIdx.x;

    if (t < 128) s[t] = (t < nb) ? g_bsum[t] : 0;
    __syncthreads();

    // prefix (exclusive) for this block = sum of s[0..bid-1]; total = sum all.
    // 128-wide inclusive scan in shared (cheap; only first 128 threads).
    if (t < 128) {
        int v = s[t];
        for (int off = 1; off < 128; off <<= 1) {
            int u = (t >= off) ? s[t - off] : 0;
            __syncthreads();
            s[t] = v + u;
            v = s[t];
            __syncthreads();
        }
    } else {
        for (int off = 1; off < 128; off <<= 1) { __syncthreads(); __syncthreads(); }
    }

    int prefix = (bid > 0) ? s[bid - 1] : 0;

    int i = bid * 1024 + t;
    if (i < n) {
        int o = g_off[i] + prefix;
        g_off[i] = o;
        g_pos[i] = o;
    }
    if (bid == nb - 1 && t == 0) g_off[n] = s[nb - 1];
}

// ===========================================================================
// Bin edges into CSR order; 4 edges per thread.
// ===========================================================================
__global__ void bin_kernel(const int*   __restrict__ erow,
                           const int*   __restrict__ ecol,
                           const float* __restrict__ evals,
                           int n_edges) {
    int t = blockIdx.x * blockDim.x + threadIdx.x;
    int base = t * 4;
    if (base + 3 < n_edges) {
        int4   rr = reinterpret_cast<const int4*>(erow)[t];
        int4   cc = reinterpret_cast<const int4*>(ecol)[t];
        float4 vv = reinterpret_cast<const float4*>(evals)[t];
        int p0 = atomicAdd(&g_pos[rr.x], 1);
        int p1 = atomicAdd(&g_pos[rr.y], 1);
        int p2 = atomicAdd(&g_pos[rr.z], 1);
        int p3 = atomicAdd(&g_pos[rr.w], 1);
        g_edges[p0] = make_int2(cc.x, __float_as_int(vv.x));
        g_edges[p1] = make_int2(cc.y, __float_as_int(vv.y));
        g_edges[p2] = make_int2(cc.z, __float_as_int(vv.z));
        g_edges[p3] = make_int2(cc.w, __float_as_int(vv.w));
    } else {
        for (int e = base; e < n_edges; e++) {
            int p = atomicAdd(&g_pos[erow[e]], 1);
            g_edges[p] = make_int2(ecol[e], __float_as_int(evals[e]));
        }
    }
}

// ===========================================================================
// Aggregate: warp per dst node, rolling prefetch depth 4 (unchanged — at the
// L2 gather floor).
// ===========================================================================
__global__ void agg_kernel(const float* __restrict__ x, int n_nodes) {
    int warp = (blockIdx.x * blockDim.x + threadIdx.x) >> 5;
    if (warp >= n_nodes) return;
    int lane = threadIdx.x & 31;

    int beg = g_off[warp];
    int end = g_off[warp + 1];

    const float4* x4 = reinterpret_cast<const float4*>(x);
    float4 acc = make_float4(0.f, 0.f, 0.f, 0.f);

    int2 pf[4];
    #pragma unroll
    for (int j = 0; j < 4; j++)
        pf[j] = (beg + j < end) ? __ldg(&g_edges[beg + j]) : make_int2(0, 0);

    for (int p = beg; p < end; p += 4) {
        int2 cur[4];
        #pragma unroll
        for (int j = 0; j < 4; j++) cur[j] = pf[j];
        #pragma unroll
        for (int j = 0; j < 4; j++)
            pf[j] = (p + 4 + j < end) ? __ldg(&g_edges[p + 4 + j]) : make_int2(0, 0);
        #pragma unroll
        for (int j = 0; j < 4; j++) {
            if (p + j < end) {
                float v = __int_as_float(cur[j].y);
                float4 g = x4[(size_t)cur[j].x * 32 + lane];
                acc.x = fmaf(v, g.x, acc.x);
                acc.y = fmaf(v, g.y, acc.y);
                acc.z = fmaf(v, g.z, acc.z);
                acc.w = fmaf(v, g.w, acc.w);
            }
        }
    }

    reinterpret_cast<float4*>(g_agg)[(size_t)warp * 32 + lane] = acc;
}

// ===========================================================================
// Tensor-core GEMM via mma.sync m16n8k16 bf16 (split, 3 terms).
// Now 512 threads / 16 warps per CTA: warp grid 4(M)x4(N), warp = 32x32 out.
// ===========================================================================
#define P 136
#define TILE_BYTES (128 * P * 2)
#define SMEM_AHI 0
#define SMEM_ALO (TILE_BYTES)
#define SMEM_BHI (2 * TILE_BYTES)
#define SMEM_BLO (3 * TILE_BYTES)
#define SMEM_TOTAL (4 * TILE_BYTES)

__device__ __forceinline__ uint32_t smem_u32(const void* p) {
    uint32_t a;
    asm("{ .reg .u64 t; cvta.to.shared.u64 t, %1; cvt.u32.u64 %0, t; }"
        : "=r"(a) : "l"(p));
    return a;
}

__device__ __forceinline__ void ldsm_x4(uint32_t addr, uint32_t& r0, uint32_t& r1,
                                        uint32_t& r2, uint32_t& r3) {
    asm volatile("ldmatrix.sync.aligned.m8n8.x4.shared.b16 {%0,%1,%2,%3}, [%4];"
                 : "=r"(r0), "=r"(r1), "=r"(r2), "=r"(r3) : "r"(addr));
}

__device__ __forceinline__ void mma_bf16(float& d0, float& d1, float& d2, float& d3,
                                         uint32_t a0, uint32_t a1, uint32_t a2, uint32_t a3,
                                         uint32_t b0, uint32_t b1) {
    asm volatile("mma.sync.aligned.m16n8k16.row.col.f32.bf16.bf16.f32 "
                 "{%0,%1,%2,%3}, {%4,%5,%6,%7}, {%8,%9}, {%0,%1,%2,%3};"
                 : "+f"(d0), "+f"(d1), "+f"(d2), "+f"(d3)
                 : "r"(a0), "r"(a1), "r"(a2), "r"(a3), "r"(b0), "r"(b1));
}

__device__ __forceinline__ void split2(float a, float b, uint32_t& h, uint32_t& l) {
    __nv_bfloat16 ha = __float2bfloat16(a);
    __nv_bfloat16 hb = __float2bfloat16(b);
    __nv_bfloat16 la = __float2bfloat16(a - __bfloat162float(ha));
    __nv_bfloat16 lb = __float2bfloat16(b - __bfloat162float(hb));
    h = (uint32_t)__bfloat16_as_ushort(ha) | ((uint32_t)__bfloat16_as_ushort(hb) << 16);
    l = (uint32_t)__bfloat16_as_ushort(la) | ((uint32_t)__bfloat16_as_ushort(lb) << 16);
}

__global__ void __launch_bounds__(512, 1)
gemm_mma_kernel(float* __restrict__ C, int n) {
    extern __shared__ char smem[];
    uint32_t sbase = smem_u32(smem);

    int tid  = threadIdx.x;
    int lane = tid & 31;
    int wid  = tid >> 5;
    int row0 = blockIdx.x << 7;

    // ---- Stage B (hi+lo), 512 threads ----
    {
        const uint4* sh = reinterpret_cast<const uint4*>(g_Whi);
        const uint4* sl = reinterpret_cast<const uint4*>(g_Wlo);
        #pragma unroll
        for (int i = 0; i < 4; i++) {
            int idx = tid + i * 512;           // 2048 uint4 per image
            int r = idx >> 4, c = idx & 15;
            int off = r * (P * 2) + c * 16;
            *reinterpret_cast<uint4*>(smem + SMEM_BHI + off) = sh[idx];
            *reinterpret_cast<uint4*>(smem + SMEM_BLO + off) = sl[idx];
        }
    }
    // ---- Load + split A tile ----
    {
        const float4* ag = reinterpret_cast<const float4*>(g_agg);
        #pragma unroll
        for (int i = 0; i < 8; i++) {
            int idx = tid + i * 512;           // 4096 float4
            int r = idx >> 5, c4 = idx & 31;
            float4 v = make_float4(0.f, 0.f, 0.f, 0.f);
            if (row0 + r < n) v = ag[(size_t)(row0 + r) * 32 + c4];
            uint32_t h0, l0, h1, l1;
            split2(v.x, v.y, h0, l0);
            split2(v.z, v.w, h1, l1);
            int off = r * (P * 2) + c4 * 8;
            *reinterpret_cast<uint2*>(smem + SMEM_AHI + off) = make_uint2(h0, h1);
            *reinterpret_cast<uint2*>(smem + SMEM_ALO + off) = make_uint2(l0, l1);
        }
    }
    __syncthreads();

    // ---- Warp tiling: 4 (M) x 4 (N); warp -> 32x32 output ----
    int wm = wid >> 2;            // 0..3
    int wn = wid & 3;             // 0..3

    int loffA = (lane & 15) * P + (lane >> 4) * 8;
    int loffB = ((lane & 7) + ((lane >> 4) & 1) * 8) * P + ((lane >> 3) & 1) * 8;

    uint32_t aHi = sbase + SMEM_AHI + 2 * (loffA + wm * 32 * P);
    uint32_t aLo = sbase + SMEM_ALO + 2 * (loffA + wm * 32 * P);
    uint32_t bHi = sbase + SMEM_BHI + 2 * (loffB + wn * 32 * P);
    uint32_t bLo = sbase + SMEM_BLO + 2 * (loffB + wn * 32 * P);

    float acc[2][4][4];
    #pragma unroll
    for (int i = 0; i < 2; i++)
        #pragma unroll
        for (int j = 0; j < 4; j++)
            #pragma unroll
            for (int q = 0; q < 4; q++) acc[i][j][q] = 0.f;

    #pragma unroll
    for (int ks = 0; ks < 8; ks++) {
        uint32_t ah[2][4], al[2][4];
        #pragma unroll
        for (int mt = 0; mt < 2; mt++) {
            uint32_t off = (uint32_t)(mt * 16 * P * 2 + ks * 32);
            ldsm_x4(aHi + off, ah[mt][0], ah[mt][1], ah[mt][2], ah[mt][3]);
            ldsm_x4(aLo + off, al[mt][0], al[mt][1], al[mt][2], al[mt][3]);
        }
        uint32_t bh[4][2], bl[4][2];
        #pragma unroll
        for (int nt2 = 0; nt2 < 2; nt2++) {
            uint32_t off = (uint32_t)(nt2 * 16 * P * 2 + ks * 32);
            ldsm_x4(bHi + off, bh[nt2 * 2][0], bh[nt2 * 2][1],
                               bh[nt2 * 2 + 1][0], bh[nt2 * 2 + 1][1]);
            ldsm_x4(bLo + off, bl[nt2 * 2][0], bl[nt2 * 2][1],
                               bl[nt2 * 2 + 1][0], bl[nt2 * 2 + 1][1]);
        }
        #pragma unroll
        for (int mt = 0; mt < 2; mt++)
            #pragma unroll
            for (int nt = 0; nt < 4; nt++) {
                float* d = acc[mt][nt];
                mma_bf16(d[0], d[1], d[2], d[3],
                         ah[mt][0], ah[mt][1], ah[mt][2], ah[mt][3],
                         bh[nt][0], bh[nt][1]);
                mma_bf16(d[0], d[1], d[2], d[3],
                         ah[mt][0], ah[mt][1], ah[mt][2], ah[mt][3],
                         bl[nt][0], bl[nt][1]);
                mma_bf16(d[0], d[1], d[2], d[3],
                         al[mt][0], al[mt][1], al[mt][2], al[mt][3],
                         bh[nt][0], bh[nt][1]);
            }
    }

    int tr = lane >> 2;
    int tc = (lane & 3) * 2;
    #pragma unroll
    for (int mt = 0; mt < 2; mt++) {
        int r_a = row0 + wm * 32 + mt * 16 + tr;
        int r_b = r_a + 8;
        #pragma unroll
        for (int nt = 0; nt < 4; nt++) {
            int col = wn * 32 + nt * 8 + tc;
            if (r_a < n)
                *reinterpret_cast<float2*>(C + (size_t)r_a * D + col) =
                    make_float2(acc[mt][nt][0], acc[mt][nt][1]);
            if (r_b < n)
                *reinterpret_cast<float2*>(C + (size_t)r_b * D + col) =
                    make_float2(acc[mt][nt][2], acc[mt][nt][3]);
        }
    }
}

// ===========================================================================
// Launch
// ===========================================================================
extern "C" void kernel_launch(void* const* d_in, const int* in_sizes, int n_in,
                              void* d_out, int out_size) {
    const float* x     = (const float*)d_in[0];
    const int*   erow  = (const int*)  d_in[1];
    const int*   ecol  = (const int*)  d_in[2];
    const float* evals = (const float*)d_in[3];
    const float* W     = (const float*)d_in[4];
    float*       out   = (float*)d_out;

    int n_nodes = in_sizes[0] / D;   // 100000
    int n_edges = in_sizes[1];       // 1600000

    int scan_blocks = (n_nodes + 1023) / 1024;   // 98 <= 128

    // 1) zero degrees + W prep (merged)
    prep_kernel<<<192, 256>>>(W, n_nodes);
    // 2) histogram
    {
        int nthread = (n_edges + 3) / 4;
        hist_kernel<<<(nthread + 255) / 256, 256>>>(erow, n_edges);
    }
    // 3) scan (2 kernels; scanB folded into scanC)
    scanA_kernel<<<scan_blocks, 1024>>>(n_nodes);
    scanC_kernel<<<scan_blocks, 1024>>>(scan_blocks, n_nodes);
    // 4) bin
    {
        int nthread = (n_edges + 3) / 4;
        bin_kernel<<<(nthread + 255) / 256, 256>>>(erow, ecol, evals, n_edges);
    }
    // 5) aggregate
    agg_kernel<<<(n_nodes + 7) / 8, 256>>>(x, n_nodes);
    // 6) tensor-core GEMM agg @ W -> out
    {
        cudaFuncSetAttribute(gemm_mma_kernel,
                             cudaFuncAttributeMaxDynamicSharedMemorySize, SMEM_TOTAL);
        int blocks = (n_nodes + 127) / 128;
        gemm_mma_kernel<<<blocks, 512, SMEM_TOTAL>>>(out, n_nodes);
    }
}